// round 1
// baseline (speedup 1.0000x reference)
#include <cuda_runtime.h>

// One thread per sample. Entire 1300-step CCP + final-solve pipeline is
// register-resident; only X is read and score(X_opt) written.

__global__ __launch_bounds__(256) void strat_kernel(
    const float* __restrict__ X,
    const float* __restrict__ w,
    const float* __restrict__ b,
    const float* __restrict__ v,
    float* __restrict__ out,
    int n)
{
    int i = blockIdx.x * blockDim.x + threadIdx.x;
    if (i >= n) return;

    // Broadcast scalars (all lanes same address -> L1 broadcast, negligible)
    const float w0 = w[0], w1 = w[1];
    const float bb = b[0];
    const float v0 = v[0], v1 = v[1];

    const float2 Xi = reinterpret_cast<const float2*>(X)[i];
    const float X0 = Xi.x, X1 = Xi.y;

    // Precomputed constants
    const float bm  = bb - 1.0f;          // for s = score - 1 (g side)
    const float bp  = bb + 1.0f;          // for s = score + 1 (f side)
    const float nhw0 = -0.5f * w0;        // -0.5*slope*w
    const float nhw1 = -0.5f * w1;
    const float qv0 = 0.475f * v0;        // COST*(1-EPS)*v = 0.5*0.95*v
    const float qv1 = 0.475f * v1;

    // Inner solves start from clip(X)
    const float Xc0 = fminf(fmaxf(X0, -10.0f), 10.0f);
    const float Xc1 = fminf(fmaxf(X1, -10.0f), 10.0f);

    // CCP iterate (starts at X, NOT clipped — matches fori_loop init)
    float xt0 = X0, xt1 = X1;
    float x0 = Xc0, x1 = Xc1;

    // rounds 0..10: fd at xt, 100 steps.  round 11: fd at XT, 200 steps (DELTA).
    #pragma unroll 1
    for (int round = 0; round < 12; ++round) {
        // fd = 0.5 * (st / sqrt(st^2+1)) * w   with st = score(xt)+1
        float st = __fmaf_rn(xt0, w0, __fmaf_rn(xt1, w1, bp));
        float ct = st * rsqrtf(__fmaf_rn(st, st, 1.0f));   // st/sqrt(st^2+1)
        // A_i = fd_i + 0.05*X_i   (since  x + grad = 0.95 x + fd + 0.05 X - ...)
        float A0 = __fmaf_rn(ct, -nhw0, 0.05f * X0);       // ct*0.5*w0 + 0.05*X0
        float A1 = __fmaf_rn(ct, -nhw1, 0.05f * X1);

        const int nsteps = (round == 11) ? 200 : 100;

        x0 = Xc0; x1 = Xc1;
        #pragma unroll 4
        for (int k = 0; k < nsteps; ++k) {
            // s = score(x) - 1
            float s  = __fmaf_rn(x0, w0, __fmaf_rn(x1, w1, bm));
            float sr = s * rsqrtf(__fmaf_rn(s, s, 1.0f));  // s/sqrt(s^2+1)

            // d.v with d = x - X  (kept in reference form for sign fidelity)
            float d0 = x0 - X0;
            float d1 = x1 - X1;
            float dv = __fmaf_rn(d1, v1, d0 * v0);

            // y = 0.95*x + A - sr*(0.5*w) - [dv>0]*0.475*v
            float y0 = __fmaf_rn(sr, nhw0, __fmaf_rn(0.95f, x0, A0));
            float y1 = __fmaf_rn(sr, nhw1, __fmaf_rn(0.95f, x1, A1));
            if (dv > 0.0f) { y0 -= qv0; y1 -= qv1; }

            x0 = fminf(fmaxf(y0, -10.0f), 10.0f);
            x1 = fminf(fmaxf(y1, -10.0f), 10.0f);
        }
        xt0 = x0; xt1 = x1;
    }

    // out = score(X_opt) = X_opt @ w + b
    out[i] = __fmaf_rn(x0, w0, __fmaf_rn(x1, w1, bb));
}

extern "C" void kernel_launch(void* const* d_in, const int* in_sizes, int n_in,
                              void* d_out, int out_size)
{
    const float* X = (const float*)d_in[0];  // [B, 2]
    const float* w = (const float*)d_in[1];  // [2]
    const float* b = (const float*)d_in[2];  // [1]
    const float* v = (const float*)d_in[3];  // [2]
    float* out = (float*)d_out;              // [B]

    int n = in_sizes[0] / 2;                 // B samples
    int threads = 256;
    int blocks = (n + threads - 1) / threads;
    strat_kernel<<<blocks, threads>>>(X, w, b, v, out, n);
}